// round 13
// baseline (speedup 1.0000x reference)
#include <cuda_runtime.h>

// GlitchSampler: masked scatter of random glitch windows into X, plus y labels.
//
// R13 = R12 resubmit (broker failed twice; no kernel evidence against).
// R11 (best: 8.16us) + L2 evict_last policy on all bulk reads.
//   Mechanism: working set (X 16.8MB + touched glitch ~8.4MB + out 16.8MB
//   ~= 42MB) fits in L2 (~126MB). Across graph replays the 16.8MB/replay
//   dirty write stream churns L2 and can evict the read set under default
//   LRU; pinning reads at evict_last keeps them resident -> warm-state read
//   hits. Reads keep the L2::256B prefetch (doubles fetch granularity on
//   cold misses). Metadata front-loaded before the branch (2-hop chain).
//
// Shapes: X [512,2,4096] f32, y [512] f32, glitch_{h,l} [2048,16384] f32,
//         masks/idx/starts [2,512] int32.
// Output: concat(Xo.flatten(), yo.flatten()) = 4,194,304 + 512 f32.

#define Bn 512
#define Cn 2
#define Kn 4096
#define Tn 16384
#define MIN_START 3584
#define TPB 256

__device__ __forceinline__ unsigned long long mk_evict_last_policy()
{
    unsigned long long p;
    asm("createpolicy.fractional.L2::evict_last.b64 %0, 1.0;" : "=l"(p));
    return p;
}

__device__ __forceinline__ float4 ldg_pf4(const float4* p, unsigned long long pol)
{
    float4 v;
    asm volatile("ld.global.nc.L2::cache_hint.L2::256B.v4.f32 {%0,%1,%2,%3}, [%4], %5;"
                 : "=f"(v.x), "=f"(v.y), "=f"(v.z), "=f"(v.w)
                 : "l"(p), "l"(pol));
    return v;
}

__device__ __forceinline__ float ldg_pf1(const float* p, unsigned long long pol)
{
    float v;
    asm volatile("ld.global.nc.L2::cache_hint.L2::256B.f32 %0, [%1], %2;"
                 : "=f"(v)
                 : "l"(p), "l"(pol));
    return v;
}

__global__ void __launch_bounds__(TPB)
glitch_sampler_kernel(const float* __restrict__ X,
                      const float* __restrict__ y,
                      const float* __restrict__ gh,
                      const float* __restrict__ gl,
                      const int*   __restrict__ masks,
                      const int*   __restrict__ idx,
                      const int*   __restrict__ starts,
                      float* __restrict__ out)
{
    const int row = blockIdx.x;                 // 0..1023 rows; block 1024 = y tail
    const int tid = threadIdx.x;

    if (row < Bn * Cn) {
        const int b  = row >> 1;                // X layout [B,C,K]: row = b*2 + c
        const int c  = row & 1;
        const int cb = c * Bn + b;              // metadata layout [C,B]

        // front-load ALL metadata (no branch-dependent loads)
        const int m  = masks[cb];
        const int gi = idx[cb];
        const int gs = starts[cb];

        const unsigned long long pol = mk_evict_last_policy();

        // both candidate sources computed before the branch
        const float* __restrict__ g   = (c == 0) ? gh : gl;
        const float* __restrict__ gsv = g + (long)gi * Tn + (gs + MIN_START);
        const float* __restrict__ xs  = X + (long)row * Kn;

        float* __restrict__ dstf = out + (long)row * Kn;

        const float* srcf = m ? gsv : xs;
        const bool aligned16 = (((size_t)srcf & 15u) == 0u);  // X path always true

        if (aligned16) {
            // aligned float4 copy: 4 front-batched prefetching loads, 4 stores
            const float4* __restrict__ s4 = (const float4*)srcf + tid;
            float4*       __restrict__ d4 = (float4*)dstf + tid;
            float4 v0 = ldg_pf4(s4 +   0, pol);
            float4 v1 = ldg_pf4(s4 + 256, pol);
            float4 v2 = ldg_pf4(s4 + 512, pol);
            float4 v3 = ldg_pf4(s4 + 768, pol);
            d4[0]   = v0;
            d4[256] = v1;
            d4[512] = v2;
            d4[768] = v3;
        } else {
            // interleaved coalesced scalars: thread t owns floats {t + 256j}.
            // 16 independent prefetching loads, then 16 coalesced stores.
            float f[16];
            #pragma unroll
            for (int j = 0; j < 16; ++j)
                f[j] = ldg_pf1(srcf + tid + 256 * j, pol);
            #pragma unroll
            for (int j = 0; j < 16; ++j)
                dstf[tid + 256 * j] = f[j];
        }
    } else {
        // tail block: y output (512 elements, 256 threads x 2)
        #pragma unroll
        for (int i = 0; i < Bn / TPB; ++i) {
            const int b = i * TPB + tid;
            float v = y[b];
            if (masks[0 * Bn + b] != 0) v -= 2.0f;
            if (masks[1 * Bn + b] != 0) v -= 4.0f;
            out[(long)Bn * Cn * Kn + b] = v;
        }
    }
}

extern "C" void kernel_launch(void* const* d_in, const int* in_sizes, int n_in,
                              void* d_out, int out_size)
{
    const float* X      = (const float*)d_in[0];
    const float* y      = (const float*)d_in[1];
    const float* gh     = (const float*)d_in[2];
    const float* gl     = (const float*)d_in[3];
    const int*   masks  = (const int*)  d_in[4];
    const int*   idx    = (const int*)  d_in[5];
    const int*   starts = (const int*)  d_in[6];
    float* out = (float*)d_out;

    glitch_sampler_kernel<<<Bn * Cn + 1, TPB>>>(X, y, gh, gl, masks, idx, starts, out);
}

// round 14
// speedup vs baseline: 1.0036x; 1.0036x over previous
#include <cuda_runtime.h>

// GlitchSampler: masked scatter of random glitch windows into X, plus y labels.
//
// R14 = R11 (verified best: 8.16us) + streaming (evict-first) STORES.
//   R13's evict_last-on-reads regressed (8.93us): fraction=1.0 overflowed the
//   protected-capacity quota. This round attacks the same L2-churn mechanism
//   from the write side instead: `out` is write-only during replay, so its
//   16.8MB/replay of dirty lines are pure L2 pollution. __stcs stores mark
//   them evict-first, preserving default-priority capacity for the X/glitch
//   read set. Read path identical to R11 (L2::256B prefetch, nc).
//
// Shapes: X [512,2,4096] f32, y [512] f32, glitch_{h,l} [2048,16384] f32,
//         masks/idx/starts [2,512] int32.
// Output: concat(Xo.flatten(), yo.flatten()) = 4,194,304 + 512 f32.

#define Bn 512
#define Cn 2
#define Kn 4096
#define Tn 16384
#define MIN_START 3584
#define TPB 256

__device__ __forceinline__ float4 ldg_pf4(const float4* p)
{
    float4 v;
    asm volatile("ld.global.nc.L2::256B.v4.f32 {%0,%1,%2,%3}, [%4];"
                 : "=f"(v.x), "=f"(v.y), "=f"(v.z), "=f"(v.w)
                 : "l"(p));
    return v;
}

__device__ __forceinline__ float ldg_pf1(const float* p)
{
    float v;
    asm volatile("ld.global.nc.L2::256B.f32 %0, [%1];"
                 : "=f"(v)
                 : "l"(p));
    return v;
}

__global__ void __launch_bounds__(TPB)
glitch_sampler_kernel(const float* __restrict__ X,
                      const float* __restrict__ y,
                      const float* __restrict__ gh,
                      const float* __restrict__ gl,
                      const int*   __restrict__ masks,
                      const int*   __restrict__ idx,
                      const int*   __restrict__ starts,
                      float* __restrict__ out)
{
    const int row = blockIdx.x;                 // 0..1023 rows; block 1024 = y tail
    const int tid = threadIdx.x;

    if (row < Bn * Cn) {
        const int b  = row >> 1;                // X layout [B,C,K]: row = b*2 + c
        const int c  = row & 1;
        const int cb = c * Bn + b;              // metadata layout [C,B]

        // front-load ALL metadata (no branch-dependent loads)
        const int m  = masks[cb];
        const int gi = idx[cb];
        const int gs = starts[cb];

        // both candidate sources computed before the branch
        const float* __restrict__ g   = (c == 0) ? gh : gl;
        const float* __restrict__ gsv = g + (long)gi * Tn + (gs + MIN_START);
        const float* __restrict__ xs  = X + (long)row * Kn;

        float* __restrict__ dstf = out + (long)row * Kn;

        const float* srcf = m ? gsv : xs;
        const bool aligned16 = (((size_t)srcf & 15u) == 0u);  // X path always true

        if (aligned16) {
            // aligned float4 copy: 4 front-batched prefetching loads,
            // 4 streaming stores
            const float4* __restrict__ s4 = (const float4*)srcf + tid;
            float4*       __restrict__ d4 = (float4*)dstf + tid;
            float4 v0 = ldg_pf4(s4 +   0);
            float4 v1 = ldg_pf4(s4 + 256);
            float4 v2 = ldg_pf4(s4 + 512);
            float4 v3 = ldg_pf4(s4 + 768);
            __stcs(d4 +   0, v0);
            __stcs(d4 + 256, v1);
            __stcs(d4 + 512, v2);
            __stcs(d4 + 768, v3);
        } else {
            // interleaved coalesced scalars: thread t owns floats {t + 256j}.
            // 16 independent prefetching loads, then 16 coalesced streaming stores.
            float f[16];
            #pragma unroll
            for (int j = 0; j < 16; ++j)
                f[j] = ldg_pf1(srcf + tid + 256 * j);
            #pragma unroll
            for (int j = 0; j < 16; ++j)
                __stcs(dstf + tid + 256 * j, f[j]);
        }
    } else {
        // tail block: y output (512 elements, 256 threads x 2)
        #pragma unroll
        for (int i = 0; i < Bn / TPB; ++i) {
            const int b = i * TPB + tid;
            float v = y[b];
            if (masks[0 * Bn + b] != 0) v -= 2.0f;
            if (masks[1 * Bn + b] != 0) v -= 4.0f;
            __stcs(out + (long)Bn * Cn * Kn + b, v);
        }
    }
}

extern "C" void kernel_launch(void* const* d_in, const int* in_sizes, int n_in,
                              void* d_out, int out_size)
{
    const float* X      = (const float*)d_in[0];
    const float* y      = (const float*)d_in[1];
    const float* gh     = (const float*)d_in[2];
    const float* gl     = (const float*)d_in[3];
    const int*   masks  = (const int*)  d_in[4];
    const int*   idx    = (const int*)  d_in[5];
    const int*   starts = (const int*)  d_in[6];
    float* out = (float*)d_out;

    glitch_sampler_kernel<<<Bn * Cn + 1, TPB>>>(X, y, gh, gl, masks, idx, starts, out);
}

// round 15
// speedup vs baseline: 1.0898x; 1.0859x over previous
#include <cuda_runtime.h>

// GlitchSampler: masked scatter of random glitch windows into X, plus y labels.
//
// R15 = exact R11 resubmit — LOCK-IN + reproducibility check of the best
// measured kernel (8.16us). Both cache-policy variants regressed
// (R13 evict_last reads: 8.93us; R14 evict-first stores: 8.90us), so the
// default L2 replacement is near-optimal for this ~42MB working set.
//
// Winning ingredients (verified 8.77 -> 8.16us):
//   1) L2::256B prefetch hints on all bulk reads — each block reads a
//      contiguous 16KB span, so each demand load also drags the adjacent
//      128B line into L2: double fetch granularity per round trip.
//   2) metadata (masks/idx/starts) loaded unconditionally up front and both
//      candidate base addresses computed BEFORE the branch: masked-path
//      dependent chain is 2 memory hops, not 3.
//   3) 1024 row-blocks x 256 threads + y tail; aligned float4 path for
//      unmasked rows and 16B-aligned masked windows; interleaved coalesced
//      scalar path otherwise.
//
// Shapes: X [512,2,4096] f32, y [512] f32, glitch_{h,l} [2048,16384] f32,
//         masks/idx/starts [2,512] int32.
// Output: concat(Xo.flatten(), yo.flatten()) = 4,194,304 + 512 f32.

#define Bn 512
#define Cn 2
#define Kn 4096
#define Tn 16384
#define MIN_START 3584
#define TPB 256

__device__ __forceinline__ float4 ldg_pf4(const float4* p)
{
    float4 v;
    asm volatile("ld.global.nc.L2::256B.v4.f32 {%0,%1,%2,%3}, [%4];"
                 : "=f"(v.x), "=f"(v.y), "=f"(v.z), "=f"(v.w)
                 : "l"(p));
    return v;
}

__device__ __forceinline__ float ldg_pf1(const float* p)
{
    float v;
    asm volatile("ld.global.nc.L2::256B.f32 %0, [%1];"
                 : "=f"(v)
                 : "l"(p));
    return v;
}

__global__ void __launch_bounds__(TPB)
glitch_sampler_kernel(const float* __restrict__ X,
                      const float* __restrict__ y,
                      const float* __restrict__ gh,
                      const float* __restrict__ gl,
                      const int*   __restrict__ masks,
                      const int*   __restrict__ idx,
                      const int*   __restrict__ starts,
                      float* __restrict__ out)
{
    const int row = blockIdx.x;                 // 0..1023 rows; block 1024 = y tail
    const int tid = threadIdx.x;

    if (row < Bn * Cn) {
        const int b  = row >> 1;                // X layout [B,C,K]: row = b*2 + c
        const int c  = row & 1;
        const int cb = c * Bn + b;              // metadata layout [C,B]

        // front-load ALL metadata (no branch-dependent loads)
        const int m  = masks[cb];
        const int gi = idx[cb];
        const int gs = starts[cb];

        // both candidate sources computed before the branch
        const float* __restrict__ g   = (c == 0) ? gh : gl;
        const float* __restrict__ gsv = g + (long)gi * Tn + (gs + MIN_START);
        const float* __restrict__ xs  = X + (long)row * Kn;

        float* __restrict__ dstf = out + (long)row * Kn;

        const float* srcf = m ? gsv : xs;
        const bool aligned16 = (((size_t)srcf & 15u) == 0u);  // X path always true

        if (aligned16) {
            // aligned float4 copy: 4 front-batched prefetching loads, 4 stores
            const float4* __restrict__ s4 = (const float4*)srcf + tid;
            float4*       __restrict__ d4 = (float4*)dstf + tid;
            float4 v0 = ldg_pf4(s4 +   0);
            float4 v1 = ldg_pf4(s4 + 256);
            float4 v2 = ldg_pf4(s4 + 512);
            float4 v3 = ldg_pf4(s4 + 768);
            d4[0]   = v0;
            d4[256] = v1;
            d4[512] = v2;
            d4[768] = v3;
        } else {
            // interleaved coalesced scalars: thread t owns floats {t + 256j}.
            // 16 independent prefetching loads, then 16 coalesced stores.
            float f[16];
            #pragma unroll
            for (int j = 0; j < 16; ++j)
                f[j] = ldg_pf1(srcf + tid + 256 * j);
            #pragma unroll
            for (int j = 0; j < 16; ++j)
                dstf[tid + 256 * j] = f[j];
        }
    } else {
        // tail block: y output (512 elements, 256 threads x 2)
        #pragma unroll
        for (int i = 0; i < Bn / TPB; ++i) {
            const int b = i * TPB + tid;
            float v = y[b];
            if (masks[0 * Bn + b] != 0) v -= 2.0f;
            if (masks[1 * Bn + b] != 0) v -= 4.0f;
            out[(long)Bn * Cn * Kn + b] = v;
        }
    }
}

extern "C" void kernel_launch(void* const* d_in, const int* in_sizes, int n_in,
                              void* d_out, int out_size)
{
    const float* X      = (const float*)d_in[0];
    const float* y      = (const float*)d_in[1];
    const float* gh     = (const float*)d_in[2];
    const float* gl     = (const float*)d_in[3];
    const int*   masks  = (const int*)  d_in[4];
    const int*   idx    = (const int*)  d_in[5];
    const int*   starts = (const int*)  d_in[6];
    float* out = (float*)d_out;

    glitch_sampler_kernel<<<Bn * Cn + 1, TPB>>>(X, y, gh, gl, masks, idx, starts, out);
}